// round 3
// baseline (speedup 1.0000x reference)
#include <cuda_runtime.h>
#include <cuda_bf16.h>

#define CIN   64
#define COUT  64
#define KK    9
#define HH    128
#define WW    128
#define HW    (HH*WW)
#define NBATCH 4
#define THREADS 256
#define CHALF 32                    // couts per CTA
#define SMEM_BYTES (CIN*KK*CHALF*4) // 73728 B

// NHWC scratch for x: xt[n][y][x][c]
__device__ float g_xt[(size_t)NBATCH * HW * CIN];

typedef unsigned long long u64t;

__device__ __forceinline__ u64t fma2(u64t a, u64t b, u64t c) {
    u64t d;
    asm("fma.rn.f32x2 %0, %1, %2, %3;" : "=l"(d) : "l"(a), "l"(b), "l"(c));
    return d;
}
__device__ __forceinline__ u64t mul2(u64t a, u64t b) {
    u64t d;
    asm("mul.rn.f32x2 %0, %1, %2;" : "=l"(d) : "l"(a), "l"(b));
    return d;
}
__device__ __forceinline__ u64t pack2(float lo, float hi) {
    u64t d;
    asm("mov.b64 %0, {%1, %2};" : "=l"(d) : "f"(lo), "f"(hi));
    return d;
}
__device__ __forceinline__ void unpack2(u64t v, float& lo, float& hi) {
    asm("mov.b64 {%0, %1}, %2;" : "=f"(lo), "=f"(hi) : "l"(v));
}

struct Corner {
    int i00, i01, i10, i11;
    float w00, w01, w10, w11;
};

__device__ __forceinline__ Corner make_corner(int ho, int wo, int ky, int kx,
                                              float offy, float offx, float m) {
    Corner r;
    const float py = (float)(ho - 1 + ky) + offy;
    const float px = (float)(wo - 1 + kx) + offx;
    const float fy = floorf(py), fx = floorf(px);
    const float ly = py - fy, lx = px - fx;
    const int y0 = (int)fy, x0 = (int)fx;
    const int y1 = y0 + 1,  x1 = x0 + 1;
    const bool vy0 = (y0 >= 0) & (y0 < HH);
    const bool vy1 = (y1 >= 0) & (y1 < HH);
    const bool vx0 = (x0 >= 0) & (x0 < WW);
    const bool vx1 = (x1 >= 0) & (x1 < WW);
    r.w00 = (vy0 && vx0) ? (1.f - ly) * (1.f - lx) * m : 0.f;
    r.w01 = (vy0 && vx1) ? (1.f - ly) * lx         * m : 0.f;
    r.w10 = (vy1 && vx0) ? ly         * (1.f - lx) * m : 0.f;
    r.w11 = (vy1 && vx1) ? ly         * lx         * m : 0.f;
    const int cy0 = min(max(y0, 0), HH - 1);
    const int cy1 = min(max(y1, 0), HH - 1);
    const int cx0 = min(max(x0, 0), WW - 1);
    const int cx1 = min(max(x1, 0), WW - 1);
    r.i00 = cy0 * WW + cx0;
    r.i01 = cy0 * WW + cx1;
    r.i10 = cy1 * WW + cx0;
    r.i11 = cy1 * WW + cx1;
    return r;
}

// NCHW -> NHWC transpose: x[n][c][p] -> g_xt[n][p][c]
__global__ __launch_bounds__(256)
void transpose_kernel(const float* __restrict__ x) {
    __shared__ float s[32][CIN + 1];
    const int pbase = blockIdx.x * 32;
    const int n     = blockIdx.y;
    const int tid   = threadIdx.x;
    const float* xn = x + (size_t)n * CIN * HW;
    float* xtn      = g_xt + (size_t)n * HW * CIN;

    #pragma unroll
    for (int it = 0; it < 8; it++) {
        const int idx = it * 256 + tid;
        const int c = idx >> 5;
        const int p = idx & 31;
        s[p][c] = xn[(size_t)c * HW + pbase + p];
    }
    __syncthreads();
    #pragma unroll
    for (int it = 0; it < 8; it++) {
        const int idx = it * 256 + tid;
        const int p = idx >> 6;
        const int c = idx & 63;
        xtn[(size_t)(pbase + p) * CIN + c] = s[p][c];
    }
}

__global__ __launch_bounds__(THREADS, 2)
void dcnv2_kernel(const float* __restrict__ offset,
                  const float* __restrict__ mask,
                  const float* __restrict__ weight,
                  const float* __restrict__ bias,
                  float* __restrict__ out) {
    extern __shared__ float wk[];  // [576][32] for this CTA's cout half

    const int tid  = threadIdx.x;
    const int half = blockIdx.y;
    const int obase = half * CHALF;

    for (int i = tid; i < CIN * KK * CHALF; i += THREADS) {
        const int o  = i & (CHALF - 1);
        const int ck = i >> 5;
        wk[i] = weight[(obase + o) * (CIN * KK) + ck];
    }
    __syncthreads();

    const int pix0 = blockIdx.x * (2 * THREADS) + tid;
    const int pix1 = pix0 + THREADS;
    const int n    = pix0 >> 14;
    const int rem0 = pix0 & 16383, rem1 = pix1 & 16383;
    const int ho0 = rem0 >> 7, wo0 = rem0 & 127;
    const int ho1 = rem1 >> 7, wo1 = rem1 & 127;

    u64t acc0[CHALF / 2], acc1[CHALF / 2];
    #pragma unroll
    for (int j = 0; j < CHALF / 2; j++) {
        const float b0 = bias[obase + 2 * j];
        const float b1 = bias[obase + 2 * j + 1];
        acc0[j] = pack2(b0, b1);
        acc1[j] = pack2(b0, b1);
    }

    const float* xa    = g_xt + (size_t)n * HW * CIN;
    const float* offp0 = offset + ((size_t)(n * 18) * HH + ho0) * WW + wo0;
    const float* offp1 = offset + ((size_t)(n * 18) * HH + ho1) * WW + wo1;
    const float* mp0   = mask   + ((size_t)(n *  9) * HH + ho0) * WW + wo0;
    const float* mp1   = mask   + ((size_t)(n *  9) * HH + ho1) * WW + wo1;

    #pragma unroll
    for (int k = 0; k < KK; k++) {
        const int ky = k / 3, kx = k % 3;
        const Corner ca = make_corner(ho0, wo0, ky, kx,
                                      offp0[(2 * k) * HW], offp0[(2 * k + 1) * HW],
                                      mp0[k * HW]);
        const Corner cb = make_corner(ho1, wo1, ky, kx,
                                      offp1[(2 * k) * HW], offp1[(2 * k + 1) * HW],
                                      mp1[k * HW]);

        // packed bilinear weights
        const u64t wa00 = pack2(ca.w00, ca.w00), wa01 = pack2(ca.w01, ca.w01);
        const u64t wa10 = pack2(ca.w10, ca.w10), wa11 = pack2(ca.w11, ca.w11);
        const u64t wb00 = pack2(cb.w00, cb.w00), wb01 = pack2(cb.w01, cb.w01);
        const u64t wb10 = pack2(cb.w10, cb.w10), wb11 = pack2(cb.w11, cb.w11);

        // channel-contiguous corner pointers (16B aligned)
        const ulonglong2* pa00 = (const ulonglong2*)(xa + (size_t)ca.i00 * CIN);
        const ulonglong2* pa01 = (const ulonglong2*)(xa + (size_t)ca.i01 * CIN);
        const ulonglong2* pa10 = (const ulonglong2*)(xa + (size_t)ca.i10 * CIN);
        const ulonglong2* pa11 = (const ulonglong2*)(xa + (size_t)ca.i11 * CIN);
        const ulonglong2* pb00 = (const ulonglong2*)(xa + (size_t)cb.i00 * CIN);
        const ulonglong2* pb01 = (const ulonglong2*)(xa + (size_t)cb.i01 * CIN);
        const ulonglong2* pb10 = (const ulonglong2*)(xa + (size_t)cb.i10 * CIN);
        const ulonglong2* pb11 = (const ulonglong2*)(xa + (size_t)cb.i11 * CIN);

        #pragma unroll 4
        for (int cq = 0; cq < CIN / 4; cq++) {     // 4 channels per iter
            const ulonglong2 A00 = pa00[cq], A01 = pa01[cq];
            const ulonglong2 A10 = pa10[cq], A11 = pa11[cq];
            const ulonglong2 B00 = pb00[cq], B01 = pb01[cq];
            const ulonglong2 B10 = pb10[cq], B11 = pb11[cq];

            #pragma unroll
            for (int h = 0; h < 2; h++) {          // 2 channel-pairs
                const u64t ax00 = h ? A00.y : A00.x;
                const u64t ax01 = h ? A01.y : A01.x;
                const u64t ax10 = h ? A10.y : A10.x;
                const u64t ax11 = h ? A11.y : A11.x;
                const u64t bx00 = h ? B00.y : B00.x;
                const u64t bx01 = h ? B01.y : B01.x;
                const u64t bx10 = h ? B10.y : B10.x;
                const u64t bx11 = h ? B11.y : B11.x;

                const u64t va2 = fma2(wa11, ax11, fma2(wa10, ax10,
                                 fma2(wa01, ax01, mul2(wa00, ax00))));
                const u64t vb2 = fma2(wb11, bx11, fma2(wb10, bx10,
                                 fma2(wb01, bx01, mul2(wb00, bx00))));
                float va0, va1, vb0, vb1;
                unpack2(va2, va0, va1);
                unpack2(vb2, vb0, vb1);

                #pragma unroll
                for (int s = 0; s < 2; s++) {       // 2 channels in the pair
                    const int c = cq * 4 + h * 2 + s;
                    const u64t vva = pack2(s ? va1 : va0, s ? va1 : va0);
                    const u64t vvb = pack2(s ? vb1 : vb0, s ? vb1 : vb0);
                    const ulonglong2* w2 = (const ulonglong2*)(wk + (c * KK + k) * CHALF);
                    #pragma unroll
                    for (int j = 0; j < CHALF / 4; j++) {
                        const ulonglong2 wv = w2[j];
                        acc0[2 * j]     = fma2(vva, wv.x, acc0[2 * j]);
                        acc0[2 * j + 1] = fma2(vva, wv.y, acc0[2 * j + 1]);
                        acc1[2 * j]     = fma2(vvb, wv.x, acc1[2 * j]);
                        acc1[2 * j + 1] = fma2(vvb, wv.y, acc1[2 * j + 1]);
                    }
                }
            }
        }
    }

    float* op0 = out + ((size_t)n * COUT + obase) * HW + ho0 * WW + wo0;
    float* op1 = out + ((size_t)n * COUT + obase) * HW + ho1 * WW + wo1;
    #pragma unroll
    for (int j = 0; j < CHALF / 2; j++) {
        float lo, hi;
        unpack2(acc0[j], lo, hi);
        op0[(2 * j) * HW] = lo;
        op0[(2 * j + 1) * HW] = hi;
        unpack2(acc1[j], lo, hi);
        op1[(2 * j) * HW] = lo;
        op1[(2 * j + 1) * HW] = hi;
    }
}

extern "C" void kernel_launch(void* const* d_in, const int* in_sizes, int n_in,
                              void* d_out, int out_size) {
    const float* x      = (const float*)d_in[0];
    const float* offset = (const float*)d_in[1];
    const float* mask   = (const float*)d_in[2];
    const float* weight = (const float*)d_in[3];
    const float* bias   = (const float*)d_in[4];
    float* out = (float*)d_out;

    cudaFuncSetAttribute(dcnv2_kernel,
                         cudaFuncAttributeMaxDynamicSharedMemorySize, SMEM_BYTES);

    dim3 tgrid(HW / 32, NBATCH);
    transpose_kernel<<<tgrid, 256>>>(x);

    const int total = NBATCH * HH * WW;
    dim3 grid(total / (2 * THREADS), 2);
    dcnv2_kernel<<<grid, THREADS, SMEM_BYTES>>>(offset, mask, weight, bias, out);
}

// round 5
// speedup vs baseline: 2.3662x; 2.3662x over previous
#include <cuda_runtime.h>
#include <cuda_bf16.h>
#include <cstdint>

#define CIN   64
#define COUT  64
#define HH    128
#define WW    128
#define HW    (HH*WW)
#define NB    4
#define NTAP  9
#define THREADS 256

#define LDA_B 144            // A row pitch bytes (72 bf16, 16B-aligned, ldmatrix conflict-free)
#define LDB_B 144

#define A_HI   0
#define A_LO   18432         // 128*144
#define B_HI   36864
#define B_LO   46080         // +64*144
#define BIAS_OFF 55296
#define SMEM_BYTES 55584

// pre-split weights, padded row pitch 36 u32 (72 bf16): [tap][hi/lo][c*36 + o/2]
__device__ uint32_t g_wb[NTAP][2][64 * 36];

__device__ __forceinline__ uint32_t smem_u32(const void* p) {
    uint32_t a;
    asm("{ .reg .u64 t; cvta.to.shared.u64 t, %1; cvt.u32.u64 %0, t; }" : "=r"(a) : "l"(p));
    return a;
}

// split fp32 pair (v0 -> lo half, v1 -> hi half) into bf16x2 hi + residual bf16x2 lo
__device__ __forceinline__ void split_pair(float v0, float v1, uint32_t& hi2, uint32_t& lo2) {
    asm("cvt.rn.satfinite.bf16x2.f32 %0, %1, %2;" : "=r"(hi2) : "f"(v1), "f"(v0));
    const float f0 = __uint_as_float(hi2 << 16);
    const float f1 = __uint_as_float(hi2 & 0xFFFF0000u);
    const float r0 = v0 - f0;
    const float r1 = v1 - f1;
    asm("cvt.rn.satfinite.bf16x2.f32 %0, %1, %2;" : "=r"(lo2) : "f"(r1), "f"(r0));
}

#define LDSM4(r0, r1, r2, r3, a) \
    asm volatile("ldmatrix.sync.aligned.m8n8.x4.shared.b16 {%0,%1,%2,%3}, [%4];" \
        : "=r"(r0), "=r"(r1), "=r"(r2), "=r"(r3) : "r"(a))

#define LDSM4T(r0, r1, r2, r3, a) \
    asm volatile("ldmatrix.sync.aligned.m8n8.x4.trans.shared.b16 {%0,%1,%2,%3}, [%4];" \
        : "=r"(r0), "=r"(r1), "=r"(r2), "=r"(r3) : "r"(a))

#define MMA16816(D, a0, a1, a2, a3, b0, b1) \
    asm volatile("mma.sync.aligned.m16n8k16.row.col.f32.bf16.bf16.f32 " \
        "{%0,%1,%2,%3}, {%4,%5,%6,%7}, {%8,%9}, {%0,%1,%2,%3};" \
        : "+f"((D)[0]), "+f"((D)[1]), "+f"((D)[2]), "+f"((D)[3]) \
        : "r"(a0), "r"(a1), "r"(a2), "r"(a3), "r"(b0), "r"(b1))

struct Corner { int i00, i01, i10, i11; float w00, w01, w10, w11; };

__device__ __forceinline__ Corner make_corner(int ho, int wo, int ky, int kx,
                                              float offy, float offx, float m) {
    Corner r;
    const float py = (float)(ho - 1 + ky) + offy;
    const float px = (float)(wo - 1 + kx) + offx;
    const float fy = floorf(py), fx = floorf(px);
    const float ly = py - fy, lx = px - fx;
    const int y0 = (int)fy, x0 = (int)fx;
    const int y1 = y0 + 1,  x1 = x0 + 1;
    const bool vy0 = (y0 >= 0) & (y0 < HH);
    const bool vy1 = (y1 >= 0) & (y1 < HH);
    const bool vx0 = (x0 >= 0) & (x0 < WW);
    const bool vx1 = (x1 >= 0) & (x1 < WW);
    r.w00 = (vy0 && vx0) ? (1.f - ly) * (1.f - lx) * m : 0.f;
    r.w01 = (vy0 && vx1) ? (1.f - ly) * lx         * m : 0.f;
    r.w10 = (vy1 && vx0) ? ly         * (1.f - lx) * m : 0.f;
    r.w11 = (vy1 && vx1) ? ly         * lx         * m : 0.f;
    const int cy0 = min(max(y0, 0), HH - 1);
    const int cy1 = min(max(y1, 0), HH - 1);
    const int cx0 = min(max(x0, 0), WW - 1);
    const int cx1 = min(max(x1, 0), WW - 1);
    r.i00 = cy0 * WW + cx0;
    r.i01 = cy0 * WW + cx1;
    r.i10 = cy1 * WW + cx0;
    r.i11 = cy1 * WW + cx1;
    return r;
}

// prologue: split weights to bf16 hi/lo, layout B[k=c][n=o] row-major, pitch 72 bf16
__global__ __launch_bounds__(256)
void wsplit_kernel(const float* __restrict__ weight) {
    const int t = blockIdx.x;
    for (int e = threadIdx.x; e < 64 * 32; e += 256) {
        const int c  = e >> 5;
        const int op = e & 31;
        const int o0 = 2 * op;
        const float v0 = weight[((o0)     * CIN + c) * NTAP + t];
        const float v1 = weight[((o0 + 1) * CIN + c) * NTAP + t];
        uint32_t hi2, lo2;
        split_pair(v0, v1, hi2, lo2);
        g_wb[t][0][c * 36 + op] = hi2;
        g_wb[t][1][c * 36 + op] = lo2;
    }
}

__global__ __launch_bounds__(THREADS, 3)
void dcn_mma_kernel(const float* __restrict__ x,
                    const float* __restrict__ offset,
                    const float* __restrict__ mask,
                    const float* __restrict__ bias,
                    float* __restrict__ out) {
    extern __shared__ char smem[];
    const uint32_t sbase = smem_u32(smem);
    const int tid  = threadIdx.x;
    const int wid  = tid >> 5;
    const int lane = tid & 31;

    const int n  = blockIdx.x >> 7;
    const int ho = blockIdx.x & 127;

    if (tid < COUT) ((float*)(smem + BIAS_OFF))[tid] = bias[tid];

    // producer mapping: warps 0-3 pixels 32w..32w+31 ch 0-31; warps 4-7 same pixels ch 32-63
    const int p      = (wid & 3) * 32 + lane;
    const int chbase = (wid >> 2) * 32;

    const float* xc0  = x + ((size_t)n * CIN + chbase) * HW;
    const float* offp = offset + ((n * 18) * HH + ho) * WW + p;
    const float* mp   = mask   + ((n *  9) * HH + ho) * WW + p;

    const uint32_t abyte = (uint32_t)(p * LDA_B + chbase * 2);

    // consumer mapping: warp owns pixel rows m0..m0+15, all 64 couts
    const int m0  = wid * 16;
    const int g8  = lane & 7;
    const int sel = lane >> 3;
    const uint32_t a_row  = (uint32_t)(m0 + ((sel & 1) ? 8 : 0) + g8);
    const uint32_t a_koff = (sel >> 1) ? 16u : 0u;
    const uint32_t b_row  = (uint32_t)(((sel & 1) ? 8 : 0) + g8);
    const uint32_t b_noff = (sel >> 1) ? 16u : 0u;

    float d[32];
    #pragma unroll
    for (int i = 0; i < 32; i++) d[i] = 0.f;

    for (int t = 0; t < NTAP; t++) {
        // ---- produce A tiles ----
        const int ky = t / 3, kx = t % 3;
        const Corner c = make_corner(ho, p, ky, kx,
                                     offp[(2 * t) * HW], offp[(2 * t + 1) * HW],
                                     mp[t * HW]);
        #pragma unroll 4
        for (int j = 0; j < 16; j++) {
            const float* pc = xc0 + (2 * j) * HW;
            const float a00 = __ldg(pc + c.i00);
            const float a01 = __ldg(pc + c.i01);
            const float a10 = __ldg(pc + c.i10);
            const float a11 = __ldg(pc + c.i11);
            const float b00 = __ldg(pc + HW + c.i00);
            const float b01 = __ldg(pc + HW + c.i01);
            const float b10 = __ldg(pc + HW + c.i10);
            const float b11 = __ldg(pc + HW + c.i11);
            float va = c.w00 * a00;
            va = fmaf(c.w01, a01, va);
            va = fmaf(c.w10, a10, va);
            va = fmaf(c.w11, a11, va);
            float vb = c.w00 * b00;
            vb = fmaf(c.w01, b01, vb);
            vb = fmaf(c.w10, b10, vb);
            vb = fmaf(c.w11, b11, vb);
            uint32_t hi2, lo2;
            split_pair(va, vb, hi2, lo2);
            *(uint32_t*)(smem + A_HI + abyte + 4 * j) = hi2;
            *(uint32_t*)(smem + A_LO + abyte + 4 * j) = lo2;
        }
        // ---- stage B tiles (pre-split, 576 uint4 each) ----
        {
            const uint4* gh = (const uint4*)g_wb[t][0];
            const uint4* gl = (const uint4*)g_wb[t][1];
            #pragma unroll
            for (int i = 0; i < 3; i++) {
                const int idx = i * THREADS + tid;
                if (idx < 576) {
                    ((uint4*)(smem + B_HI))[idx] = gh[idx];
                    ((uint4*)(smem + B_LO))[idx] = gl[idx];
                }
            }
        }
        __syncthreads();

        // ---- consume: 3 passes (Ahi*Bhi, Ahi*Blo, Alo*Bhi) ----
        #pragma unroll
        for (int pass = 0; pass < 3; pass++) {
            const uint32_t abase = sbase + ((pass == 2) ? A_LO : A_HI)
                                 + a_row * LDA_B + a_koff;
            const uint32_t bbase = sbase + ((pass == 1) ? B_LO : B_HI)
                                 + b_row * LDB_B + b_noff;
            #pragma unroll
            for (int ks = 0; ks < 4; ks++) {
                uint32_t a0, a1, a2, a3;
                LDSM4(a0, a1, a2, a3, abase + ks * 32);
                const uint32_t bk = bbase + (uint32_t)(ks * 16 * LDB_B);
                #pragma unroll
                for (int ntp = 0; ntp < 4; ntp++) {
                    uint32_t b0, b1, b2, b3;
                    LDSM4T(b0, b1, b2, b3, bk + ntp * 32);
                    MMA16816(d + (2 * ntp) * 4,     a0, a1, a2, a3, b0, b1);
                    MMA16816(d + (2 * ntp + 1) * 4, a0, a1, a2, a3, b2, b3);
                }
            }
        }
        __syncthreads();
    }

    // ---- epilogue: d[nt*4+i], rows m0+lane/4 (+8), cols nt*8 + 2*(lane&3) (+1) ----
    const int r0 = m0 + (lane >> 2);
    const float* bs = (const float*)(smem + BIAS_OFF);
    float* op = out + (size_t)n * COUT * HW + ho * WW;
    #pragma unroll
    for (int nt = 0; nt < 8; nt++) {
        const int c0 = nt * 8 + (lane & 3) * 2;
        const float2 bb = *(const float2*)(bs + c0);
        op[c0 * HW + r0]           = d[nt * 4 + 0] + bb.x;
        op[(c0 + 1) * HW + r0]     = d[nt * 4 + 1] + bb.y;
        op[c0 * HW + r0 + 8]       = d[nt * 4 + 2] + bb.x;
        op[(c0 + 1) * HW + r0 + 8] = d[nt * 4 + 3] + bb.y;
    }
}

extern "C" void kernel_launch(void* const* d_in, const int* in_sizes, int n_in,
                              void* d_out, int out_size) {
    const float* x      = (const float*)d_in[0];
    const float* offset = (const float*)d_in[1];
    const float* mask   = (const float*)d_in[2];
    const float* weight = (const float*)d_in[3];
    const float* bias   = (const float*)d_in[4];
    float* out = (float*)d_out;

    wsplit_kernel<<<NTAP, 256>>>(weight);

    cudaFuncSetAttribute(dcn_mma_kernel,
                         cudaFuncAttributeMaxDynamicSharedMemorySize, SMEM_BYTES);
    dcn_mma_kernel<<<NB * HH, THREADS, SMEM_BYTES>>>(x, offset, mask, bias, out);
}

// round 6
// speedup vs baseline: 2.8135x; 1.1890x over previous
#include <cuda_runtime.h>
#include <cuda_bf16.h>
#include <cstdint>

#define CIN   64
#define COUT  64
#define HH    128
#define WW    128
#define HW    (HH*WW)
#define NB    4
#define NTAP  9
#define THREADS 256

#define A_HI   0
#define A_LO   16384
#define B_HI   32768
#define B_LO   40960
#define BIAS_OFF 49152
#define SMEM_BYTES 49408

// pre-split, pre-swizzled weights: [tap][hi/lo][2048 u32] = 64 rows x 128B SW128 image
__device__ uint32_t g_wb[NTAP][2][2048];

__device__ __forceinline__ uint32_t smem_u32(const void* p) {
    uint32_t a;
    asm("{ .reg .u64 t; cvta.to.shared.u64 t, %1; cvt.u32.u64 %0, t; }" : "=r"(a) : "l"(p));
    return a;
}

// split fp32 pair (v0 -> lo half, v1 -> hi half) into bf16x2 hi + residual bf16x2 lo
__device__ __forceinline__ void split_pair(float v0, float v1, uint32_t& hi2, uint32_t& lo2) {
    asm("cvt.rn.satfinite.bf16x2.f32 %0, %1, %2;" : "=r"(hi2) : "f"(v1), "f"(v0));
    const float f0 = __uint_as_float(hi2 << 16);
    const float f1 = __uint_as_float(hi2 & 0xFFFF0000u);
    const float r0 = v0 - f0;
    const float r1 = v1 - f1;
    asm("cvt.rn.satfinite.bf16x2.f32 %0, %1, %2;" : "=r"(lo2) : "f"(r1), "f"(r0));
}

#define LDSM4(r0, r1, r2, r3, a) \
    asm volatile("ldmatrix.sync.aligned.m8n8.x4.shared.b16 {%0,%1,%2,%3}, [%4];" \
        : "=r"(r0), "=r"(r1), "=r"(r2), "=r"(r3) : "r"(a))

#define LDSM4T(r0, r1, r2, r3, a) \
    asm volatile("ldmatrix.sync.aligned.m8n8.x4.trans.shared.b16 {%0,%1,%2,%3}, [%4];" \
        : "=r"(r0), "=r"(r1), "=r"(r2), "=r"(r3) : "r"(a))

#define MMA16816(D, a0, a1, a2, a3, b0, b1) \
    asm volatile("mma.sync.aligned.m16n8k16.row.col.f32.bf16.bf16.f32 " \
        "{%0,%1,%2,%3}, {%4,%5,%6,%7}, {%8,%9}, {%0,%1,%2,%3};" \
        : "+f"((D)[0]), "+f"((D)[1]), "+f"((D)[2]), "+f"((D)[3]) \
        : "r"(a0), "r"(a1), "r"(a2), "r"(a3), "r"(b0), "r"(b1))

struct Corner { int i00, i01, i10, i11; float w00, w01, w10, w11; };

__device__ __forceinline__ Corner make_corner(int ho, int wo, int ky, int kx,
                                              float offy, float offx, float m) {
    Corner r;
    const float py = (float)(ho - 1 + ky) + offy;
    const float px = (float)(wo - 1 + kx) + offx;
    const float fy = floorf(py), fx = floorf(px);
    const float ly = py - fy, lx = px - fx;
    const int y0 = (int)fy, x0 = (int)fx;
    const int y1 = y0 + 1,  x1 = x0 + 1;
    const bool vy0 = (y0 >= 0) & (y0 < HH);
    const bool vy1 = (y1 >= 0) & (y1 < HH);
    const bool vx0 = (x0 >= 0) & (x0 < WW);
    const bool vx1 = (x1 >= 0) & (x1 < WW);
    r.w00 = (vy0 && vx0) ? (1.f - ly) * (1.f - lx) * m : 0.f;
    r.w01 = (vy0 && vx1) ? (1.f - ly) * lx         * m : 0.f;
    r.w10 = (vy1 && vx0) ? ly         * (1.f - lx) * m : 0.f;
    r.w11 = (vy1 && vx1) ? ly         * lx         * m : 0.f;
    const int cy0 = min(max(y0, 0), HH - 1);
    const int cy1 = min(max(y1, 0), HH - 1);
    const int cx0 = min(max(x0, 0), WW - 1);
    const int cx1 = min(max(x1, 0), WW - 1);
    r.i00 = cy0 * WW + cx0;
    r.i01 = cy0 * WW + cx1;
    r.i10 = cy1 * WW + cx0;
    r.i11 = cy1 * WW + cx1;
    return r;
}

// prologue: split weights to bf16 hi/lo, B[c][o] pitch 128B, SW128 swizzled
__global__ __launch_bounds__(256)
void wsplit_kernel(const float* __restrict__ weight) {
    const int t = blockIdx.x;
    for (int e = threadIdx.x; e < 64 * 32; e += 256) {
        const int c  = e >> 5;
        const int op = e & 31;          // bf16x2 pair index within row (o0 = 2*op)
        const int o0 = 2 * op;
        const float v0 = weight[((o0)     * CIN + c) * NTAP + t];
        const float v1 = weight[((o0 + 1) * CIN + c) * NTAP + t];
        uint32_t hi2, lo2;
        split_pair(v0, v1, hi2, lo2);
        const uint32_t byte = (uint32_t)(c * 128 + (((op >> 2) ^ (c & 7)) << 4) + (op & 3) * 4);
        g_wb[t][0][byte >> 2] = hi2;
        g_wb[t][1][byte >> 2] = lo2;
    }
}

__global__ __launch_bounds__(THREADS, 3)
void dcn_mma_kernel(const float* __restrict__ x,
                    const float* __restrict__ offset,
                    const float* __restrict__ mask,
                    const float* __restrict__ bias,
                    float* __restrict__ out) {
    extern __shared__ char smem[];
    const uint32_t sbase = smem_u32(smem);
    const int tid  = threadIdx.x;
    const int wid  = tid >> 5;
    const int lane = tid & 31;

    const int n  = blockIdx.x >> 7;
    const int ho = blockIdx.x & 127;

    if (tid < COUT) ((float*)(smem + BIAS_OFF))[tid] = bias[tid];

    // producer mapping: warps 0-3 pixels 32w..32w+31 ch 0-31; warps 4-7 same pixels ch 32-63
    const int p      = (wid & 3) * 32 + lane;
    const int chbase = (wid >> 2) * 32;

    const float* xc0  = x + ((size_t)n * CIN + chbase) * HW;
    const float* offp = offset + ((n * 18) * HH + ho) * WW + p;
    const float* mp   = mask   + ((n *  9) * HH + ho) * WW + p;

    const uint32_t arow_base = (uint32_t)(p * 128);
    const int gbase = chbase >> 3;        // first 16B granule this thread fills

    // consumer mapping: warp owns pixel rows m0..m0+15, all 64 couts
    const int m0  = wid * 16;
    const int g8  = lane & 7;
    const int sel = lane >> 3;
    const uint32_t ca_row = (uint32_t)(m0 + ((sel & 1) ? 8 : 0) + g8);
    const uint32_t khalf  = (uint32_t)(sel >> 1);        // granule offset for k/n half

    float d[32];
    #pragma unroll
    for (int i = 0; i < 32; i++) d[i] = 0.f;

    for (int t = 0; t < NTAP; t++) {
        // ---- produce A tiles ----
        const int ky = t / 3, kx = t % 3;
        const Corner c = make_corner(ho, p, ky, kx,
                                     offp[(2 * t) * HW], offp[(2 * t + 1) * HW],
                                     mp[t * HW]);
        #pragma unroll
        for (int jg = 0; jg < 4; jg++) {              // 4 granules of 8 channels
            uint32_t ahi[4], alo[4];
            #pragma unroll
            for (int q = 0; q < 4; q++) {             // 2 channels per q
                const float* pc = xc0 + (jg * 8 + 2 * q) * HW;
                const float a00 = __ldg(pc + c.i00);
                const float a01 = __ldg(pc + c.i01);
                const float a10 = __ldg(pc + c.i10);
                const float a11 = __ldg(pc + c.i11);
                const float b00 = __ldg(pc + HW + c.i00);
                const float b01 = __ldg(pc + HW + c.i01);
                const float b10 = __ldg(pc + HW + c.i10);
                const float b11 = __ldg(pc + HW + c.i11);
                float va = c.w00 * a00;
                va = fmaf(c.w01, a01, va);
                va = fmaf(c.w10, a10, va);
                va = fmaf(c.w11, a11, va);
                float vb = c.w00 * b00;
                vb = fmaf(c.w01, b01, vb);
                vb = fmaf(c.w10, b10, vb);
                vb = fmaf(c.w11, b11, vb);
                split_pair(va, vb, ahi[q], alo[q]);
            }
            const uint32_t byte = arow_base + (uint32_t)((((gbase + jg) ^ (p & 7)) << 4));
            *(uint4*)(smem + A_HI + byte) = make_uint4(ahi[0], ahi[1], ahi[2], ahi[3]);
            *(uint4*)(smem + A_LO + byte) = make_uint4(alo[0], alo[1], alo[2], alo[3]);
        }
        // ---- stage B tiles (pre-split + pre-swizzled, 512 uint4 each) ----
        {
            const uint4* gh = (const uint4*)g_wb[t][0];
            const uint4* gl = (const uint4*)g_wb[t][1];
            ((uint4*)(smem + B_HI))[tid]       = gh[tid];
            ((uint4*)(smem + B_HI))[tid + 256] = gh[tid + 256];
            ((uint4*)(smem + B_LO))[tid]       = gl[tid];
            ((uint4*)(smem + B_LO))[tid + 256] = gl[tid + 256];
        }
        __syncthreads();

        // ---- consume: fused (Ahi+Alo)*Bhi, then Ahi*Blo ----
        #pragma unroll
        for (int ks = 0; ks < 4; ks++) {
            const uint32_t aswz = ((uint32_t)(ks * 2) + khalf) ^ (uint32_t)g8;
            const uint32_t aoff = ca_row * 128 + (aswz << 4);
            uint32_t ah0, ah1, ah2, ah3, al0, al1, al2, al3;
            LDSM4(ah0, ah1, ah2, ah3, sbase + A_HI + aoff);
            LDSM4(al0, al1, al2, al3, sbase + A_LO + aoff);
            const uint32_t brow = (uint32_t)(ks * 16 + ((sel & 1) ? 8 : 0) + g8);
            #pragma unroll
            for (int ntp = 0; ntp < 4; ntp++) {
                const uint32_t bswz = ((uint32_t)(ntp * 2) + khalf) ^ (uint32_t)g8;
                uint32_t b0, b1, b2, b3;
                LDSM4T(b0, b1, b2, b3, sbase + B_HI + brow * 128 + (bswz << 4));
                MMA16816(d + (2 * ntp) * 4,     ah0, ah1, ah2, ah3, b0, b1);
                MMA16816(d + (2 * ntp + 1) * 4, ah0, ah1, ah2, ah3, b2, b3);
                MMA16816(d + (2 * ntp) * 4,     al0, al1, al2, al3, b0, b1);
                MMA16816(d + (2 * ntp + 1) * 4, al0, al1, al2, al3, b2, b3);
            }
        }
        #pragma unroll
        for (int ks = 0; ks < 4; ks++) {
            const uint32_t aswz = ((uint32_t)(ks * 2) + khalf) ^ (uint32_t)g8;
            const uint32_t aoff = ca_row * 128 + (aswz << 4);
            uint32_t ah0, ah1, ah2, ah3;
            LDSM4(ah0, ah1, ah2, ah3, sbase + A_HI + aoff);
            const uint32_t brow = (uint32_t)(ks * 16 + ((sel & 1) ? 8 : 0) + g8);
            #pragma unroll
            for (int ntp = 0; ntp < 4; ntp++) {
                const uint32_t bswz = ((uint32_t)(ntp * 2) + khalf) ^ (uint32_t)g8;
                uint32_t b0, b1, b2, b3;
                LDSM4T(b0, b1, b2, b3, sbase + B_LO + brow * 128 + (bswz << 4));
                MMA16816(d + (2 * ntp) * 4,     ah0, ah1, ah2, ah3, b0, b1);
                MMA16816(d + (2 * ntp + 1) * 4, ah0, ah1, ah2, ah3, b2, b3);
            }
        }
        __syncthreads();
    }

    // ---- epilogue ----
    const int r0 = m0 + (lane >> 2);
    const float* bs = (const float*)(smem + BIAS_OFF);
    float* op = out + (size_t)n * COUT * HW + ho * WW;
    #pragma unroll
    for (int nt = 0; nt < 8; nt++) {
        const int c0 = nt * 8 + (lane & 3) * 2;
        const float2 bb = *(const float2*)(bs + c0);
        op[c0 * HW + r0]           = d[nt * 4 + 0] + bb.x;
        op[(c0 + 1) * HW + r0]     = d[nt * 4 + 1] + bb.y;
        op[c0 * HW + r0 + 8]       = d[nt * 4 + 2] + bb.x;
        op[(c0 + 1) * HW + r0 + 8] = d[nt * 4 + 3] + bb.y;
    }
}

extern "C" void kernel_launch(void* const* d_in, const int* in_sizes, int n_in,
                              void* d_out, int out_size) {
    const float* x      = (const float*)d_in[0];
    const float* offset = (const float*)d_in[1];
    const float* mask   = (const float*)d_in[2];
    const float* weight = (const float*)d_in[3];
    const float* bias   = (const float*)d_in[4];
    float* out = (float*)d_out;

    wsplit_kernel<<<NTAP, 256>>>(weight);

    cudaFuncSetAttribute(dcn_mma_kernel,
                         cudaFuncAttributeMaxDynamicSharedMemorySize, SMEM_BYTES);
    dcn_mma_kernel<<<NB * HH, THREADS, SMEM_BYTES>>>(x, offset, mask, bias, out);
}

// round 7
// speedup vs baseline: 3.4514x; 1.2267x over previous
#include <cuda_runtime.h>
#include <cuda_bf16.h>
#include <cstdint>

#define CIN   64
#define COUT  64
#define HH    128
#define WW    128
#define HW    (HH*WW)
#define NB    4
#define NTAP  9
#define THREADS 256

// smem: two A stages (HI+LO each 16KB), two B stages (HI+LO each 8KB), bias
#define A_ST(s)   ((s) * 32768)
#define A_LO_OFF  16384
#define B_ST(s)   (65536 + (s) * 16384)
#define B_LO_OFF  8192
#define BIAS_OFF  98304
#define SMEM_BYTES 98560

// pre-split, pre-swizzled weights: [tap][hi/lo][2048 u32] = 64 rows x 128B SW128 image
__device__ uint32_t g_wb[NTAP][2][2048];

__device__ __forceinline__ uint32_t smem_u32(const void* p) {
    uint32_t a;
    asm("{ .reg .u64 t; cvta.to.shared.u64 t, %1; cvt.u32.u64 %0, t; }" : "=r"(a) : "l"(p));
    return a;
}

__device__ __forceinline__ void split_pair(float v0, float v1, uint32_t& hi2, uint32_t& lo2) {
    asm("cvt.rn.satfinite.bf16x2.f32 %0, %1, %2;" : "=r"(hi2) : "f"(v1), "f"(v0));
    const float f0 = __uint_as_float(hi2 << 16);
    const float f1 = __uint_as_float(hi2 & 0xFFFF0000u);
    const float r0 = v0 - f0;
    const float r1 = v1 - f1;
    asm("cvt.rn.satfinite.bf16x2.f32 %0, %1, %2;" : "=r"(lo2) : "f"(r1), "f"(r0));
}

#define LDSM4(r0, r1, r2, r3, a) \
    asm volatile("ldmatrix.sync.aligned.m8n8.x4.shared.b16 {%0,%1,%2,%3}, [%4];" \
        : "=r"(r0), "=r"(r1), "=r"(r2), "=r"(r3) : "r"(a))

#define LDSM4T(r0, r1, r2, r3, a) \
    asm volatile("ldmatrix.sync.aligned.m8n8.x4.trans.shared.b16 {%0,%1,%2,%3}, [%4];" \
        : "=r"(r0), "=r"(r1), "=r"(r2), "=r"(r3) : "r"(a))

#define MMA16816(D, a0, a1, a2, a3, b0, b1) \
    asm volatile("mma.sync.aligned.m16n8k16.row.col.f32.bf16.bf16.f32 " \
        "{%0,%1,%2,%3}, {%4,%5,%6,%7}, {%8,%9}, {%0,%1,%2,%3};" \
        : "+f"((D)[0]), "+f"((D)[1]), "+f"((D)[2]), "+f"((D)[3]) \
        : "r"(a0), "r"(a1), "r"(a2), "r"(a3), "r"(b0), "r"(b1))

#define CPASYNC16(s, g) asm volatile("cp.async.cg.shared.global [%0], [%1], 16;" :: "r"(s), "l"(g) : "memory")
#define CPCOMMIT()      asm volatile("cp.async.commit_group;" ::: "memory")
#define CPWAIT0()       asm volatile("cp.async.wait_group 0;" ::: "memory")

struct Corner { int i00, i01, i10, i11; float w00, w01, w10, w11; };

__device__ __forceinline__ Corner make_corner(int ho, int wo, int ky, int kx,
                                              float offy, float offx, float m) {
    Corner r;
    const float py = (float)(ho - 1 + ky) + offy;
    const float px = (float)(wo - 1 + kx) + offx;
    const float fy = floorf(py), fx = floorf(px);
    const float ly = py - fy, lx = px - fx;
    const int y0 = (int)fy, x0 = (int)fx;
    const int y1 = y0 + 1,  x1 = x0 + 1;
    const bool vy0 = (y0 >= 0) & (y0 < HH);
    const bool vy1 = (y1 >= 0) & (y1 < HH);
    const bool vx0 = (x0 >= 0) & (x0 < WW);
    const bool vx1 = (x1 >= 0) & (x1 < WW);
    r.w00 = (vy0 && vx0) ? (1.f - ly) * (1.f - lx) * m : 0.f;
    r.w01 = (vy0 && vx1) ? (1.f - ly) * lx         * m : 0.f;
    r.w10 = (vy1 && vx0) ? ly         * (1.f - lx) * m : 0.f;
    r.w11 = (vy1 && vx1) ? ly         * lx         * m : 0.f;
    const int cy0 = min(max(y0, 0), HH - 1);
    const int cy1 = min(max(y1, 0), HH - 1);
    const int cx0 = min(max(x0, 0), WW - 1);
    const int cx1 = min(max(x1, 0), WW - 1);
    r.i00 = cy0 * WW + cx0;
    r.i01 = cy0 * WW + cx1;
    r.i10 = cy1 * WW + cx0;
    r.i11 = cy1 * WW + cx1;
    return r;
}

// prologue kernel: split weights to bf16 hi/lo, B[c][o] pitch 128B, SW128 swizzled
__global__ __launch_bounds__(256)
void wsplit_kernel(const float* __restrict__ weight) {
    const int t = blockIdx.x;
    for (int e = threadIdx.x; e < 64 * 32; e += 256) {
        const int c  = e >> 5;
        const int op = e & 31;
        const int o0 = 2 * op;
        const float v0 = weight[((o0)     * CIN + c) * NTAP + t];
        const float v1 = weight[((o0 + 1) * CIN + c) * NTAP + t];
        uint32_t hi2, lo2;
        split_pair(v0, v1, hi2, lo2);
        const uint32_t byte = (uint32_t)(c * 128 + (((op >> 2) ^ (c & 7)) << 4) + (op & 3) * 4);
        g_wb[t][0][byte >> 2] = hi2;
        g_wb[t][1][byte >> 2] = lo2;
    }
}

__global__ __launch_bounds__(THREADS, 2)
void dcn_mma_kernel(const float* __restrict__ x,
                    const float* __restrict__ offset,
                    const float* __restrict__ mask,
                    const float* __restrict__ bias,
                    float* __restrict__ out) {
    extern __shared__ char smem[];
    const uint32_t sbase = smem_u32(smem);
    const int tid  = threadIdx.x;
    const int wid  = tid >> 5;
    const int lane = tid & 31;

    const int n  = blockIdx.x >> 7;
    const int ho = blockIdx.x & 127;

    if (tid < COUT) ((float*)(smem + BIAS_OFF))[tid] = bias[tid];

    // producer mapping
    const int p      = (wid & 3) * 32 + lane;
    const int chbase = (wid >> 2) * 32;
    const float* xc0  = x + ((size_t)n * CIN + chbase) * HW;
    const float* offp = offset + ((n * 18) * HH + ho) * WW + p;
    const float* mp   = mask   + ((n *  9) * HH + ho) * WW + p;
    const uint32_t arow_base = (uint32_t)(p * 128);
    const int gbase = chbase >> 3;

    // consumer mapping
    const int m0  = wid * 16;
    const int g8  = lane & 7;
    const int sel = lane >> 3;
    const uint32_t ca_row = (uint32_t)(m0 + ((sel & 1) ? 8 : 0) + g8);
    const uint32_t khalf  = (uint32_t)(sel >> 1);

    float d[32];
    #pragma unroll
    for (int i = 0; i < 32; i++) d[i] = 0.f;

    // ---- prologue: stage B(0) via cp.async, produce A(0) into stage 0 ----
    {
        const uint4* gh = (const uint4*)g_wb[0][0];
        const uint4* gl = (const uint4*)g_wb[0][1];
        CPASYNC16(sbase + B_ST(0) + tid * 16,                      (const char*)(gh + tid));
        CPASYNC16(sbase + B_ST(0) + (tid + 256) * 16,              (const char*)(gh + tid + 256));
        CPASYNC16(sbase + B_ST(0) + B_LO_OFF + tid * 16,           (const char*)(gl + tid));
        CPASYNC16(sbase + B_ST(0) + B_LO_OFF + (tid + 256) * 16,   (const char*)(gl + tid + 256));
        CPCOMMIT();
        const Corner c = make_corner(ho, p, 0, 0, offp[0], offp[HW], mp[0]);
        #pragma unroll
        for (int jg = 0; jg < 4; jg++) {
            uint32_t ahi[4], alo[4];
            #pragma unroll
            for (int q = 0; q < 4; q++) {
                const float* pc = xc0 + (jg * 8 + 2 * q) * HW;
                const float a00 = __ldg(pc + c.i00);
                const float a01 = __ldg(pc + c.i01);
                const float a10 = __ldg(pc + c.i10);
                const float a11 = __ldg(pc + c.i11);
                const float b00 = __ldg(pc + HW + c.i00);
                const float b01 = __ldg(pc + HW + c.i01);
                const float b10 = __ldg(pc + HW + c.i10);
                const float b11 = __ldg(pc + HW + c.i11);
                float va = c.w00 * a00;
                va = fmaf(c.w01, a01, va);
                va = fmaf(c.w10, a10, va);
                va = fmaf(c.w11, a11, va);
                float vb = c.w00 * b00;
                vb = fmaf(c.w01, b01, vb);
                vb = fmaf(c.w10, b10, vb);
                vb = fmaf(c.w11, b11, vb);
                split_pair(va, vb, ahi[q], alo[q]);
            }
            const uint32_t byte = arow_base + (uint32_t)((((gbase + jg) ^ (p & 7)) << 4));
            *(uint4*)(smem + A_ST(0) + byte)            = make_uint4(ahi[0], ahi[1], ahi[2], ahi[3]);
            *(uint4*)(smem + A_ST(0) + A_LO_OFF + byte) = make_uint4(alo[0], alo[1], alo[2], alo[3]);
        }
        CPWAIT0();
    }
    __syncthreads();

    // ---- main pipelined loop ----
    #pragma unroll 1
    for (int t = 0; t < NTAP; t++) {
        const int s  = t & 1;
        const int s1 = s ^ 1;
        const bool hasNext = (t < NTAP - 1);

        Corner cn;
        if (hasNext) {
            const int tn = t + 1;
            const int ky = tn / 3, kx = tn % 3;
            cn = make_corner(ho, p, ky, kx,
                             offp[(2 * tn) * HW], offp[(2 * tn + 1) * HW], mp[tn * HW]);
            const uint4* gh = (const uint4*)g_wb[tn][0];
            const uint4* gl = (const uint4*)g_wb[tn][1];
            CPASYNC16(sbase + B_ST(s1) + tid * 16,                    (const char*)(gh + tid));
            CPASYNC16(sbase + B_ST(s1) + (tid + 256) * 16,            (const char*)(gh + tid + 256));
            CPASYNC16(sbase + B_ST(s1) + B_LO_OFF + tid * 16,         (const char*)(gl + tid));
            CPASYNC16(sbase + B_ST(s1) + B_LO_OFF + (tid + 256) * 16, (const char*)(gl + tid + 256));
            CPCOMMIT();
        }

        const uint32_t aH = sbase + A_ST(s);
        const uint32_t aL = aH + A_LO_OFF;
        const uint32_t bH = sbase + B_ST(s);
        const uint32_t bL = bH + B_LO_OFF;

        #pragma unroll
        for (int ks = 0; ks < 4; ks++) {
            // -- issue gather chunk (granule ks) for tap t+1 --
            float v[32];
            if (hasNext) {
                #pragma unroll
                for (int q = 0; q < 4; q++) {
                    const float* pc = xc0 + (ks * 8 + 2 * q) * HW;
                    v[8 * q + 0] = __ldg(pc + cn.i00);
                    v[8 * q + 1] = __ldg(pc + cn.i01);
                    v[8 * q + 2] = __ldg(pc + cn.i10);
                    v[8 * q + 3] = __ldg(pc + cn.i11);
                    v[8 * q + 4] = __ldg(pc + HW + cn.i00);
                    v[8 * q + 5] = __ldg(pc + HW + cn.i01);
                    v[8 * q + 6] = __ldg(pc + HW + cn.i10);
                    v[8 * q + 7] = __ldg(pc + HW + cn.i11);
                }
            }

            // -- consume k-slice ks of tap t (merged HI/LO passes) --
            {
                const uint32_t aswz = ((uint32_t)(ks * 2) + khalf) ^ (uint32_t)g8;
                const uint32_t aoff = ca_row * 128 + (aswz << 4);
                uint32_t ah0, ah1, ah2, ah3, al0, al1, al2, al3;
                LDSM4(ah0, ah1, ah2, ah3, aH + aoff);
                LDSM4(al0, al1, al2, al3, aL + aoff);
                const uint32_t brow = (uint32_t)(ks * 16 + ((sel & 1) ? 8 : 0) + g8);
                #pragma unroll
                for (int ntp = 0; ntp < 4; ntp++) {
                    const uint32_t bswz = ((uint32_t)(ntp * 2) + khalf) ^ (uint32_t)g8;
                    uint32_t b0, b1, b2, b3;
                    LDSM4T(b0, b1, b2, b3, bH + brow * 128 + (bswz << 4));
                    MMA16816(d + (2 * ntp) * 4,     ah0, ah1, ah2, ah3, b0, b1);
                    MMA16816(d + (2 * ntp + 1) * 4, ah0, ah1, ah2, ah3, b2, b3);
                    MMA16816(d + (2 * ntp) * 4,     al0, al1, al2, al3, b0, b1);
                    MMA16816(d + (2 * ntp + 1) * 4, al0, al1, al2, al3, b2, b3);
                    uint32_t c0, c1, c2, c3;
                    LDSM4T(c0, c1, c2, c3, bL + brow * 128 + (bswz << 4));
                    MMA16816(d + (2 * ntp) * 4,     ah0, ah1, ah2, ah3, c0, c1);
                    MMA16816(d + (2 * ntp + 1) * 4, ah0, ah1, ah2, ah3, c2, c3);
                }
            }

            // -- finish gather chunk: bilinear combine, split, STS into stage s1 --
            if (hasNext) {
                uint32_t ahi[4], alo[4];
                #pragma unroll
                for (int q = 0; q < 4; q++) {
                    float va = cn.w00 * v[8 * q + 0];
                    va = fmaf(cn.w01, v[8 * q + 1], va);
                    va = fmaf(cn.w10, v[8 * q + 2], va);
                    va = fmaf(cn.w11, v[8 * q + 3], va);
                    float vb = cn.w00 * v[8 * q + 4];
                    vb = fmaf(cn.w01, v[8 * q + 5], vb);
                    vb = fmaf(cn.w10, v[8 * q + 6], vb);
                    vb = fmaf(cn.w11, v[8 * q + 7], vb);
                    split_pair(va, vb, ahi[q], alo[q]);
                }
                const uint32_t byte = arow_base + (uint32_t)((((gbase + ks) ^ (p & 7)) << 4));
                *(uint4*)(smem + A_ST(s1) + byte)            = make_uint4(ahi[0], ahi[1], ahi[2], ahi[3]);
                *(uint4*)(smem + A_ST(s1) + A_LO_OFF + byte) = make_uint4(alo[0], alo[1], alo[2], alo[3]);
            }
        }

        if (hasNext) CPWAIT0();
        __syncthreads();
    }

    // ---- epilogue ----
    const int r0 = m0 + (lane >> 2);
    const float* bs = (const float*)(smem + BIAS_OFF);
    float* op = out + (size_t)n * COUT * HW + ho * WW;
    #pragma unroll
    for (int nt = 0; nt < 8; nt++) {
        const int c0 = nt * 8 + (lane & 3) * 2;
        const float2 bb = *(const float2*)(bs + c0);
        op[c0 * HW + r0]           = d[nt * 4 + 0] + bb.x;
        op[(c0 + 1) * HW + r0]     = d[nt * 4 + 1] + bb.y;
        op[c0 * HW + r0 + 8]       = d[nt * 4 + 2] + bb.x;
        op[(c0 + 1) * HW + r0 + 8] = d[nt * 4 + 3] + bb.y;
    }
}

extern "C" void kernel_launch(void* const* d_in, const int* in_sizes, int n_in,
                              void* d_out, int out_size) {
    const float* x      = (const float*)d_in[0];
    const float* offset = (const float*)d_in[1];
    const float* mask   = (const float*)d_in[2];
    const float* weight = (const float*)d_in[3];
    const float* bias   = (const float*)d_in[4];
    float* out = (float*)d_out;

    wsplit_kernel<<<NTAP, 256>>>(weight);

    cudaFuncSetAttribute(dcn_mma_kernel,
                         cudaFuncAttributeMaxDynamicSharedMemorySize, SMEM_BYTES);
    dcn_mma_kernel<<<NB * HH, THREADS, SMEM_BYTES>>>(x, offset, mask, bias, out);
}

// round 8
// speedup vs baseline: 4.6865x; 1.3579x over previous
#include <cuda_runtime.h>
#include <cuda_bf16.h>
#include <cstdint>

#define CIN   64
#define COUT  64
#define HH    128
#define WW    128
#define HW    (HH*WW)
#define NB    4
#define NTAP  9
#define THREADS 256

// smem: two A stages (HI+LO each 16KB), two B stages (HI+LO each 8KB), corner buf, bias
#define A_ST(s)   ((s) * 32768)
#define A_LO_OFF  16384
#define B_ST(s)   (65536 + (s) * 16384)
#define B_LO_OFF  8192
#define CBUF      98304
#define BIAS_OFF  102400
#define SMEM_BYTES 102656

// NHWC scratch: xt[n][p][c]
__device__ float g_xt[(size_t)NB * HW * CIN];
// pre-split, pre-swizzled weights: [tap][hi/lo][2048 u32] = 64 rows x 128B SW128 image
__device__ uint32_t g_wb[NTAP][2][2048];

__device__ __forceinline__ uint32_t smem_u32(const void* p) {
    uint32_t a;
    asm("{ .reg .u64 t; cvta.to.shared.u64 t, %1; cvt.u32.u64 %0, t; }" : "=r"(a) : "l"(p));
    return a;
}

__device__ __forceinline__ void split_pair(float v0, float v1, uint32_t& hi2, uint32_t& lo2) {
    asm("cvt.rn.satfinite.bf16x2.f32 %0, %1, %2;" : "=r"(hi2) : "f"(v1), "f"(v0));
    const float f0 = __uint_as_float(hi2 << 16);
    const float f1 = __uint_as_float(hi2 & 0xFFFF0000u);
    const float r0 = v0 - f0;
    const float r1 = v1 - f1;
    asm("cvt.rn.satfinite.bf16x2.f32 %0, %1, %2;" : "=r"(lo2) : "f"(r1), "f"(r0));
}

#define LDSM4(r0, r1, r2, r3, a) \
    asm volatile("ldmatrix.sync.aligned.m8n8.x4.shared.b16 {%0,%1,%2,%3}, [%4];" \
        : "=r"(r0), "=r"(r1), "=r"(r2), "=r"(r3) : "r"(a))

#define LDSM4T(r0, r1, r2, r3, a) \
    asm volatile("ldmatrix.sync.aligned.m8n8.x4.trans.shared.b16 {%0,%1,%2,%3}, [%4];" \
        : "=r"(r0), "=r"(r1), "=r"(r2), "=r"(r3) : "r"(a))

#define MMA16816(D, a0, a1, a2, a3, b0, b1) \
    asm volatile("mma.sync.aligned.m16n8k16.row.col.f32.bf16.bf16.f32 " \
        "{%0,%1,%2,%3}, {%4,%5,%6,%7}, {%8,%9}, {%0,%1,%2,%3};" \
        : "+f"((D)[0]), "+f"((D)[1]), "+f"((D)[2]), "+f"((D)[3]) \
        : "r"(a0), "r"(a1), "r"(a2), "r"(a3), "r"(b0), "r"(b1))

#define CPASYNC16(s, g) asm volatile("cp.async.cg.shared.global [%0], [%1], 16;" :: "r"(s), "l"(g) : "memory")
#define CPCOMMIT()      asm volatile("cp.async.commit_group;" ::: "memory")
#define CPWAIT0()       asm volatile("cp.async.wait_group 0;" ::: "memory")

struct Corner { int i00, i01, i10, i11; float w00, w01, w10, w11; };

__device__ __forceinline__ Corner make_corner(int ho, int wo, int ky, int kx,
                                              float offy, float offx, float m) {
    Corner r;
    const float py = (float)(ho - 1 + ky) + offy;
    const float px = (float)(wo - 1 + kx) + offx;
    const float fy = floorf(py), fx = floorf(px);
    const float ly = py - fy, lx = px - fx;
    const int y0 = (int)fy, x0 = (int)fx;
    const int y1 = y0 + 1,  x1 = x0 + 1;
    const bool vy0 = (y0 >= 0) & (y0 < HH);
    const bool vy1 = (y1 >= 0) & (y1 < HH);
    const bool vx0 = (x0 >= 0) & (x0 < WW);
    const bool vx1 = (x1 >= 0) & (x1 < WW);
    r.w00 = (vy0 && vx0) ? (1.f - ly) * (1.f - lx) * m : 0.f;
    r.w01 = (vy0 && vx1) ? (1.f - ly) * lx         * m : 0.f;
    r.w10 = (vy1 && vx0) ? ly         * (1.f - lx) * m : 0.f;
    r.w11 = (vy1 && vx1) ? ly         * lx         * m : 0.f;
    const int cy0 = min(max(y0, 0), HH - 1);
    const int cy1 = min(max(y1, 0), HH - 1);
    const int cx0 = min(max(x0, 0), WW - 1);
    const int cx1 = min(max(x1, 0), WW - 1);
    r.i00 = cy0 * WW + cx0;
    r.i01 = cy0 * WW + cx1;
    r.i10 = cy1 * WW + cx0;
    r.i11 = cy1 * WW + cx1;
    return r;
}

// NCHW -> NHWC transpose
__global__ __launch_bounds__(256)
void transpose_kernel(const float* __restrict__ x) {
    __shared__ float s[32][CIN + 1];
    const int pbase = blockIdx.x * 32;
    const int n     = blockIdx.y;
    const int tid   = threadIdx.x;
    const float* xn = x + (size_t)n * CIN * HW;
    float* xtn      = g_xt + (size_t)n * HW * CIN;
    #pragma unroll
    for (int it = 0; it < 8; it++) {
        const int idx = it * 256 + tid;
        const int c = idx >> 5;
        const int p = idx & 31;
        s[p][c] = xn[(size_t)c * HW + pbase + p];
    }
    __syncthreads();
    #pragma unroll
    for (int it = 0; it < 8; it++) {
        const int idx = it * 256 + tid;
        const int p = idx >> 6;
        const int c = idx & 63;
        xtn[(size_t)(pbase + p) * CIN + c] = s[p][c];
    }
}

// split weights to bf16 hi/lo, B[c][o] pitch 128B, SW128 swizzled
__global__ __launch_bounds__(256)
void wsplit_kernel(const float* __restrict__ weight) {
    const int t = blockIdx.x;
    for (int e = threadIdx.x; e < 64 * 32; e += 256) {
        const int c  = e >> 5;
        const int op = e & 31;
        const int o0 = 2 * op;
        const float v0 = weight[((o0)     * CIN + c) * NTAP + t];
        const float v1 = weight[((o0 + 1) * CIN + c) * NTAP + t];
        uint32_t hi2, lo2;
        split_pair(v0, v1, hi2, lo2);
        const uint32_t byte = (uint32_t)(c * 128 + (((op >> 2) ^ (c & 7)) << 4) + (op & 3) * 4);
        g_wb[t][0][byte >> 2] = hi2;
        g_wb[t][1][byte >> 2] = lo2;
    }
}

__global__ __launch_bounds__(THREADS, 2)
void dcn_mma_kernel(const float* __restrict__ offset,
                    const float* __restrict__ mask,
                    const float* __restrict__ bias,
                    float* __restrict__ out) {
    extern __shared__ char smem[];
    const uint32_t sbase = smem_u32(smem);
    const int tid  = threadIdx.x;
    const int wid  = tid >> 5;
    const int lane = tid & 31;

    const int n  = blockIdx.x >> 7;
    const int ho = blockIdx.x & 127;

    if (tid < COUT) ((float*)(smem + BIAS_OFF))[tid] = bias[tid];

    const int wp0 = wid * 16;                 // warp's 16 pixels
    const int myp = wp0 + (lane & 15);        // pixel for corner calc (lanes 16-31 duplicate)
    const float* xtn = g_xt + (size_t)n * HW * CIN;

    // consumer mapping (warp owns pixel rows wp0..wp0+15, all 64 couts)
    const int g8  = lane & 7;
    const int sel = lane >> 3;
    const uint32_t ca_row = (uint32_t)(wp0 + ((sel & 1) ? 8 : 0) + g8);
    const uint32_t khalf  = (uint32_t)(sel >> 1);

    float d[32];
    #pragma unroll
    for (int i = 0; i < 32; i++) d[i] = 0.f;

    // corner calc for tap tt into cbuf (warp-local)
    auto calc_corners = [&](int tt) {
        const int ky = tt / 3, kx = tt % 3;
        const float offy = offset[((n * 18 + 2 * tt)     * HH + ho) * WW + myp];
        const float offx = offset[((n * 18 + 2 * tt + 1) * HH + ho) * WW + myp];
        const float m    = mask[((n * 9 + tt) * HH + ho) * WW + myp];
        const Corner c = make_corner(ho, myp, ky, kx, offy, offx, m);
        if (lane < 16) {
            *(int4*)(smem + CBUF + myp * 32)        = make_int4(c.i00, c.i01, c.i10, c.i11);
            *(float4*)(smem + CBUF + myp * 32 + 16) = make_float4(c.w00, c.w01, c.w10, c.w11);
        }
        __syncwarp();
    };

    // ---- prologue: corners(0), B(0) cp.async, produce A(0) ----
    calc_corners(0);
    {
        const uint4* gh = (const uint4*)g_wb[0][0];
        const uint4* gl = (const uint4*)g_wb[0][1];
        CPASYNC16(sbase + B_ST(0) + tid * 16,                      (const char*)(gh + tid));
        CPASYNC16(sbase + B_ST(0) + (tid + 256) * 16,              (const char*)(gh + tid + 256));
        CPASYNC16(sbase + B_ST(0) + B_LO_OFF + tid * 16,           (const char*)(gl + tid));
        CPASYNC16(sbase + B_ST(0) + B_LO_OFF + (tid + 256) * 16,   (const char*)(gl + tid + 256));
        CPCOMMIT();
    }
    #pragma unroll
    for (int ck = 0; ck < 4; ck++) {
        float2 v[16];
        #pragma unroll
        for (int j = 0; j < 4; j++) {
            const int px = wp0 + ck * 4 + j;
            const int4 idx = *(const int4*)(smem + CBUF + px * 32);
            v[4 * j + 0] = __ldg((const float2*)(xtn + (size_t)idx.x * CIN) + lane);
            v[4 * j + 1] = __ldg((const float2*)(xtn + (size_t)idx.y * CIN) + lane);
            v[4 * j + 2] = __ldg((const float2*)(xtn + (size_t)idx.z * CIN) + lane);
            v[4 * j + 3] = __ldg((const float2*)(xtn + (size_t)idx.w * CIN) + lane);
        }
        #pragma unroll
        for (int j = 0; j < 4; j++) {
            const int px = wp0 + ck * 4 + j;
            const float4 w = *(const float4*)(smem + CBUF + px * 32 + 16);
            float vx = w.x * v[4 * j].x;
            vx = fmaf(w.y, v[4 * j + 1].x, vx);
            vx = fmaf(w.z, v[4 * j + 2].x, vx);
            vx = fmaf(w.w, v[4 * j + 3].x, vx);
            float vy = w.x * v[4 * j].y;
            vy = fmaf(w.y, v[4 * j + 1].y, vy);
            vy = fmaf(w.z, v[4 * j + 2].y, vy);
            vy = fmaf(w.w, v[4 * j + 3].y, vy);
            uint32_t hi2, lo2;
            split_pair(vx, vy, hi2, lo2);
            const uint32_t byte = (uint32_t)(px * 128 + ((((lane >> 2) ^ (px & 7))) << 4) + (lane & 3) * 4);
            *(uint32_t*)(smem + A_ST(0) + byte)            = hi2;
            *(uint32_t*)(smem + A_ST(0) + A_LO_OFF + byte) = lo2;
        }
    }
    CPWAIT0();
    __syncthreads();

    // ---- main pipelined loop ----
    #pragma unroll 1
    for (int t = 0; t < NTAP; t++) {
        const int s  = t & 1;
        const int s1 = s ^ 1;
        const bool hasNext = (t < NTAP - 1);

        if (hasNext) {
            calc_corners(t + 1);
            const uint4* gh = (const uint4*)g_wb[t + 1][0];
            const uint4* gl = (const uint4*)g_wb[t + 1][1];
            CPASYNC16(sbase + B_ST(s1) + tid * 16,                    (const char*)(gh + tid));
            CPASYNC16(sbase + B_ST(s1) + (tid + 256) * 16,            (const char*)(gh + tid + 256));
            CPASYNC16(sbase + B_ST(s1) + B_LO_OFF + tid * 16,         (const char*)(gl + tid));
            CPASYNC16(sbase + B_ST(s1) + B_LO_OFF + (tid + 256) * 16, (const char*)(gl + tid + 256));
            CPCOMMIT();
        }

        const uint32_t aH = sbase + A_ST(s);
        const uint32_t aL = aH + A_LO_OFF;
        const uint32_t bH = sbase + B_ST(s);
        const uint32_t bL = bH + B_LO_OFF;

        #pragma unroll
        for (int ks = 0; ks < 4; ks++) {
            // -- issue gather (4 pixels x 4 corners, all 64 ch) for tap t+1 --
            float2 v[16];
            if (hasNext) {
                #pragma unroll
                for (int j = 0; j < 4; j++) {
                    const int px = wp0 + ks * 4 + j;
                    const int4 idx = *(const int4*)(smem + CBUF + px * 32);
                    v[4 * j + 0] = __ldg((const float2*)(xtn + (size_t)idx.x * CIN) + lane);
                    v[4 * j + 1] = __ldg((const float2*)(xtn + (size_t)idx.y * CIN) + lane);
                    v[4 * j + 2] = __ldg((const float2*)(xtn + (size_t)idx.z * CIN) + lane);
                    v[4 * j + 3] = __ldg((const float2*)(xtn + (size_t)idx.w * CIN) + lane);
                }
            }

            // -- consume k-slice ks of tap t --
            {
                const uint32_t aswz = ((uint32_t)(ks * 2) + khalf) ^ (uint32_t)g8;
                const uint32_t aoff = ca_row * 128 + (aswz << 4);
                uint32_t ah0, ah1, ah2, ah3, al0, al1, al2, al3;
                LDSM4(ah0, ah1, ah2, ah3, aH + aoff);
                LDSM4(al0, al1, al2, al3, aL + aoff);
                const uint32_t brow = (uint32_t)(ks * 16 + ((sel & 1) ? 8 : 0) + g8);
                #pragma unroll
                for (int ntp = 0; ntp < 4; ntp++) {
                    const uint32_t bswz = ((uint32_t)(ntp * 2) + khalf) ^ (uint32_t)g8;
                    uint32_t b0, b1, b2, b3;
                    LDSM4T(b0, b1, b2, b3, bH + brow * 128 + (bswz << 4));
                    MMA16816(d + (2 * ntp) * 4,     ah0, ah1, ah2, ah3, b0, b1);
                    MMA16816(d + (2 * ntp + 1) * 4, ah0, ah1, ah2, ah3, b2, b3);
                    MMA16816(d + (2 * ntp) * 4,     al0, al1, al2, al3, b0, b1);
                    MMA16816(d + (2 * ntp + 1) * 4, al0, al1, al2, al3, b2, b3);
                    uint32_t c0, c1, c2, c3;
                    LDSM4T(c0, c1, c2, c3, bL + brow * 128 + (bswz << 4));
                    MMA16816(d + (2 * ntp) * 4,     ah0, ah1, ah2, ah3, c0, c1);
                    MMA16816(d + (2 * ntp + 1) * 4, ah0, ah1, ah2, ah3, c2, c3);
                }
            }

            // -- combine + STS chunk into stage s1 --
            if (hasNext) {
                #pragma unroll
                for (int j = 0; j < 4; j++) {
                    const int px = wp0 + ks * 4 + j;
                    const float4 w = *(const float4*)(smem + CBUF + px * 32 + 16);
                    float vx = w.x * v[4 * j].x;
                    vx = fmaf(w.y, v[4 * j + 1].x, vx);
                    vx = fmaf(w.z, v[4 * j + 2].x, vx);
                    vx = fmaf(w.w, v[4 * j + 3].x, vx);
                    float vy = w.x * v[4 * j].y;
                    vy = fmaf(w.y, v[4 * j + 1].y, vy);
                    vy = fmaf(w.z, v[4 * j + 2].y, vy);
                    vy = fmaf(w.w, v[4 * j + 3].y, vy);
                    uint32_t hi2, lo2;
                    split_pair(vx, vy, hi2, lo2);
                    const uint32_t byte = (uint32_t)(px * 128 + ((((lane >> 2) ^ (px & 7))) << 4) + (lane & 3) * 4);
                    *(uint32_t*)(smem + A_ST(s1) + byte)            = hi2;
                    *(uint32_t*)(smem + A_ST(s1) + A_LO_OFF + byte) = lo2;
                }
            }
        }

        if (hasNext) CPWAIT0();
        __syncthreads();
    }

    // ---- epilogue ----
    const int r0 = wp0 + (lane >> 2);
    const float* bs = (const float*)(smem + BIAS_OFF);
    float* op = out + (size_t)n * COUT * HW + ho * WW;
    #pragma unroll
    for (int nt = 0; nt < 8; nt++) {
        const int c0 = nt * 8 + (lane & 3) * 2;
        const float2 bb = *(const float2*)(bs + c0);
        op[c0 * HW + r0]           = d[nt * 4 + 0] + bb.x;
        op[(c0 + 1) * HW + r0]     = d[nt * 4 + 1] + bb.y;
        op[c0 * HW + r0 + 8]       = d[nt * 4 + 2] + bb.x;
        op[(c0 + 1) * HW + r0 + 8] = d[nt * 4 + 3] + bb.y;
    }
}

extern "C" void kernel_launch(void* const* d_in, const int* in_sizes, int n_in,
                              void* d_out, int out_size) {
    const float* x      = (const float*)d_in[0];
    const float* offset = (const float*)d_in[1];
    const float* mask   = (const float*)d_in[2];
    const float* weight = (const float*)d_in[3];
    const float* bias   = (const float*)d_in[4];
    float* out = (float*)d_out;

    wsplit_kernel<<<NTAP, 256>>>(weight);
    dim3 tgrid(HW / 32, NB);
    transpose_kernel<<<tgrid, 256>>>(x);

    cudaFuncSetAttribute(dcn_mma_kernel,
                         cudaFuncAttributeMaxDynamicSharedMemorySize, SMEM_BYTES);
    dcn_mma_kernel<<<NB * HH, THREADS, SMEM_BYTES>>>(offset, mask, bias, out);
}

// round 9
// speedup vs baseline: 4.7399x; 1.0114x over previous
#include <cuda_runtime.h>
#include <cuda_bf16.h>
#include <cstdint>

#define CIN   64
#define COUT  64
#define HH    128
#define WW    128
#define HW    (HH*WW)
#define NB    4
#define NTAP  9
#define THREADS 256

// smem: two A stages (HI+LO each 16KB), two B stages (HI+LO each 8KB), corner buf, bias
#define A_ST(s)   ((s) * 32768)
#define A_LO_OFF  16384
#define B_ST(s)   (65536 + (s) * 16384)
#define B_LO_OFF  8192
#define CBUF      98304
#define BIAS_OFF  102400
#define SMEM_BYTES 102656

// NHWC scratch: xt[n][p][c]
__device__ float g_xt[(size_t)NB * HW * CIN];
// pre-split, pre-swizzled weights: [tap][hi/lo][2048 u32] = 64 rows x 128B SW128 image
__device__ uint32_t g_wb[NTAP][2][2048];

__device__ __forceinline__ uint32_t smem_u32(const void* p) {
    uint32_t a;
    asm("{ .reg .u64 t; cvta.to.shared.u64 t, %1; cvt.u32.u64 %0, t; }" : "=r"(a) : "l"(p));
    return a;
}

__device__ __forceinline__ void split_pair(float v0, float v1, uint32_t& hi2, uint32_t& lo2) {
    asm("cvt.rn.satfinite.bf16x2.f32 %0, %1, %2;" : "=r"(hi2) : "f"(v1), "f"(v0));
    const float f0 = __uint_as_float(hi2 << 16);
    const float f1 = __uint_as_float(hi2 & 0xFFFF0000u);
    const float r0 = v0 - f0;
    const float r1 = v1 - f1;
    asm("cvt.rn.satfinite.bf16x2.f32 %0, %1, %2;" : "=r"(lo2) : "f"(r1), "f"(r0));
}

#define LDSM4(r0, r1, r2, r3, a) \
    asm volatile("ldmatrix.sync.aligned.m8n8.x4.shared.b16 {%0,%1,%2,%3}, [%4];" \
        : "=r"(r0), "=r"(r1), "=r"(r2), "=r"(r3) : "r"(a))

#define LDSM4T(r0, r1, r2, r3, a) \
    asm volatile("ldmatrix.sync.aligned.m8n8.x4.trans.shared.b16 {%0,%1,%2,%3}, [%4];" \
        : "=r"(r0), "=r"(r1), "=r"(r2), "=r"(r3) : "r"(a))

#define MMA16816(D, a0, a1, a2, a3, b0, b1) \
    asm volatile("mma.sync.aligned.m16n8k16.row.col.f32.bf16.bf16.f32 " \
        "{%0,%1,%2,%3}, {%4,%5,%6,%7}, {%8,%9}, {%0,%1,%2,%3};" \
        : "+f"((D)[0]), "+f"((D)[1]), "+f"((D)[2]), "+f"((D)[3]) \
        : "r"(a0), "r"(a1), "r"(a2), "r"(a3), "r"(b0), "r"(b1))

#define CPASYNC16(s, g) asm volatile("cp.async.cg.shared.global [%0], [%1], 16;" :: "r"(s), "l"(g) : "memory")
#define CPCOMMIT()      asm volatile("cp.async.commit_group;" ::: "memory")
#define CPWAIT0()       asm volatile("cp.async.wait_group 0;" ::: "memory")

struct Corner { int i00, i01, i10, i11; float w00, w01, w10, w11; };

__device__ __forceinline__ Corner make_corner(int ho, int wo, int ky, int kx,
                                              float offy, float offx, float m) {
    Corner r;
    const float py = (float)(ho - 1 + ky) + offy;
    const float px = (float)(wo - 1 + kx) + offx;
    const float fy = floorf(py), fx = floorf(px);
    const float ly = py - fy, lx = px - fx;
    const int y0 = (int)fy, x0 = (int)fx;
    const int y1 = y0 + 1,  x1 = x0 + 1;
    const bool vy0 = (y0 >= 0) & (y0 < HH);
    const bool vy1 = (y1 >= 0) & (y1 < HH);
    const bool vx0 = (x0 >= 0) & (x0 < WW);
    const bool vx1 = (x1 >= 0) & (x1 < WW);
    r.w00 = (vy0 && vx0) ? (1.f - ly) * (1.f - lx) * m : 0.f;
    r.w01 = (vy0 && vx1) ? (1.f - ly) * lx         * m : 0.f;
    r.w10 = (vy1 && vx0) ? ly         * (1.f - lx) * m : 0.f;
    r.w11 = (vy1 && vx1) ? ly         * lx         * m : 0.f;
    const int cy0 = min(max(y0, 0), HH - 1);
    const int cy1 = min(max(y1, 0), HH - 1);
    const int cx0 = min(max(x0, 0), WW - 1);
    const int cx1 = min(max(x1, 0), WW - 1);
    r.i00 = cy0 * WW + cx0;
    r.i01 = cy0 * WW + cx1;
    r.i10 = cy1 * WW + cx0;
    r.i11 = cy1 * WW + cx1;
    return r;
}

// fused prologue: blocks [0, 2048) do NCHW->NHWC transpose; blocks [2048, 2057) split weights
#define TBLOCKS (NB * HW / 32)
__global__ __launch_bounds__(256)
void prep_kernel(const float* __restrict__ x, const float* __restrict__ weight) {
    const int bx  = blockIdx.x;
    const int tid = threadIdx.x;

    if (bx < TBLOCKS) {
        __shared__ float s[32][CIN + 1];
        const int n     = bx >> 9;            // 512 pixel-blocks per batch
        const int pbase = (bx & 511) * 32;
        const float* xn = x + (size_t)n * CIN * HW;
        float* xtn      = g_xt + (size_t)n * HW * CIN;
        #pragma unroll
        for (int it = 0; it < 8; it++) {
            const int idx = it * 256 + tid;
            const int c = idx >> 5;
            const int p = idx & 31;
            s[p][c] = xn[(size_t)c * HW + pbase + p];
        }
        __syncthreads();
        #pragma unroll
        for (int it = 0; it < 8; it++) {
            const int idx = it * 256 + tid;
            const int p = idx >> 6;
            const int c = idx & 63;
            xtn[(size_t)(pbase + p) * CIN + c] = s[p][c];
        }
    } else {
        const int t = bx - TBLOCKS;           // tap 0..8
        for (int e = tid; e < 64 * 32; e += 256) {
            const int c  = e >> 5;
            const int op = e & 31;
            const int o0 = 2 * op;
            const float v0 = weight[((o0)     * CIN + c) * NTAP + t];
            const float v1 = weight[((o0 + 1) * CIN + c) * NTAP + t];
            uint32_t hi2, lo2;
            split_pair(v0, v1, hi2, lo2);
            const uint32_t byte = (uint32_t)(c * 128 + (((op >> 2) ^ (c & 7)) << 4) + (op & 3) * 4);
            g_wb[t][0][byte >> 2] = hi2;
            g_wb[t][1][byte >> 2] = lo2;
        }
    }
}

__global__ __launch_bounds__(THREADS, 2)
void dcn_mma_kernel(const float* __restrict__ offset,
                    const float* __restrict__ mask,
                    const float* __restrict__ bias,
                    float* __restrict__ out) {
    extern __shared__ char smem[];
    const uint32_t sbase = smem_u32(smem);
    const int tid  = threadIdx.x;
    const int wid  = tid >> 5;
    const int lane = tid & 31;

    const int n  = blockIdx.x >> 7;
    const int ho = blockIdx.x & 127;

    if (tid < COUT) ((float*)(smem + BIAS_OFF))[tid] = bias[tid];

    const int wp0 = wid * 16;                 // warp's 16 pixels
    const int myp = wp0 + (lane & 15);        // pixel for corner calc (lanes 16-31 duplicate)
    const float* xtn = g_xt + (size_t)n * HW * CIN;

    // consumer mapping (warp owns pixel rows wp0..wp0+15, all 64 couts)
    const int g8  = lane & 7;
    const int sel = lane >> 3;
    const uint32_t ca_row = (uint32_t)(wp0 + ((sel & 1) ? 8 : 0) + g8);
    const uint32_t khalf  = (uint32_t)(sel >> 1);

    float d[32];
    #pragma unroll
    for (int i = 0; i < 32; i++) d[i] = 0.f;

    // corner calc for tap tt into cbuf (warp-local)
    auto calc_corners = [&](int tt) {
        const int ky = tt / 3, kx = tt % 3;
        const float offy = offset[((n * 18 + 2 * tt)     * HH + ho) * WW + myp];
        const float offx = offset[((n * 18 + 2 * tt + 1) * HH + ho) * WW + myp];
        const float m    = mask[((n * 9 + tt) * HH + ho) * WW + myp];
        const Corner c = make_corner(ho, myp, ky, kx, offy, offx, m);
        if (lane < 16) {
            *(int4*)(smem + CBUF + myp * 32)        = make_int4(c.i00, c.i01, c.i10, c.i11);
            *(float4*)(smem + CBUF + myp * 32 + 16) = make_float4(c.w00, c.w01, c.w10, c.w11);
        }
        __syncwarp();
    };

    // ---- prologue: corners(0), B(0) cp.async, produce A(0) ----
    calc_corners(0);
    {
        const uint4* gh = (const uint4*)g_wb[0][0];
        const uint4* gl = (const uint4*)g_wb[0][1];
        CPASYNC16(sbase + B_ST(0) + tid * 16,                      (const char*)(gh + tid));
        CPASYNC16(sbase + B_ST(0) + (tid + 256) * 16,              (const char*)(gh + tid + 256));
        CPASYNC16(sbase + B_ST(0) + B_LO_OFF + tid * 16,           (const char*)(gl + tid));
        CPASYNC16(sbase + B_ST(0) + B_LO_OFF + (tid + 256) * 16,   (const char*)(gl + tid + 256));
        CPCOMMIT();
    }
    #pragma unroll
    for (int ck = 0; ck < 4; ck++) {
        float2 v[16];
        #pragma unroll
        for (int j = 0; j < 4; j++) {
            const int px = wp0 + ck * 4 + j;
            const int4 idx = *(const int4*)(smem + CBUF + px * 32);
            v[4 * j + 0] = __ldg((const float2*)(xtn + (size_t)idx.x * CIN) + lane);
            v[4 * j + 1] = __ldg((const float2*)(xtn + (size_t)idx.y * CIN) + lane);
            v[4 * j + 2] = __ldg((const float2*)(xtn + (size_t)idx.z * CIN) + lane);
            v[4 * j + 3] = __ldg((const float2*)(xtn + (size_t)idx.w * CIN) + lane);
        }
        #pragma unroll
        for (int j = 0; j < 4; j++) {
            const int px = wp0 + ck * 4 + j;
            const float4 w = *(const float4*)(smem + CBUF + px * 32 + 16);
            float vx = w.x * v[4 * j].x;
            vx = fmaf(w.y, v[4 * j + 1].x, vx);
            vx = fmaf(w.z, v[4 * j + 2].x, vx);
            vx = fmaf(w.w, v[4 * j + 3].x, vx);
            float vy = w.x * v[4 * j].y;
            vy = fmaf(w.y, v[4 * j + 1].y, vy);
            vy = fmaf(w.z, v[4 * j + 2].y, vy);
            vy = fmaf(w.w, v[4 * j + 3].y, vy);
            uint32_t hi2, lo2;
            split_pair(vx, vy, hi2, lo2);
            const uint32_t byte = (uint32_t)(px * 128 + ((((lane >> 2) ^ (px & 7))) << 4) + (lane & 3) * 4);
            *(uint32_t*)(smem + A_ST(0) + byte)            = hi2;
            *(uint32_t*)(smem + A_ST(0) + A_LO_OFF + byte) = lo2;
        }
    }
    CPWAIT0();
    __syncthreads();

    // ---- main pipelined loop ----
    #pragma unroll 1
    for (int t = 0; t < NTAP; t++) {
        const int s  = t & 1;
        const int s1 = s ^ 1;
        const bool hasNext = (t < NTAP - 1);

        if (hasNext) {
            calc_corners(t + 1);
            const uint4* gh = (const uint4*)g_wb[t + 1][0];
            const uint4* gl = (const uint4*)g_wb[t + 1][1];
            CPASYNC16(sbase + B_ST(s1) + tid * 16,                    (const char*)(gh + tid));
            CPASYNC16(sbase + B_ST(s1) + (tid + 256) * 16,            (const char*)(gh + tid + 256));
            CPASYNC16(sbase + B_ST(s1) + B_LO_OFF + tid * 16,         (const char*)(gl + tid));
            CPASYNC16(sbase + B_ST(s1) + B_LO_OFF + (tid + 256) * 16, (const char*)(gl + tid + 256));
            CPCOMMIT();
        }

        const uint32_t aH = sbase + A_ST(s);
        const uint32_t aL = aH + A_LO_OFF;
        const uint32_t bH = sbase + B_ST(s);
        const uint32_t bL = bH + B_LO_OFF;

        #pragma unroll
        for (int ks = 0; ks < 4; ks++) {
            // -- issue gather (4 pixels x 4 corners, all 64 ch) for tap t+1 --
            float2 v[16];
            if (hasNext) {
                #pragma unroll
                for (int j = 0; j < 4; j++) {
                    const int px = wp0 + ks * 4 + j;
                    const int4 idx = *(const int4*)(smem + CBUF + px * 32);
                    v[4 * j + 0] = __ldg((const float2*)(xtn + (size_t)idx.x * CIN) + lane);
                    v[4 * j + 1] = __ldg((const float2*)(xtn + (size_t)idx.y * CIN) + lane);
                    v[4 * j + 2] = __ldg((const float2*)(xtn + (size_t)idx.z * CIN) + lane);
                    v[4 * j + 3] = __ldg((const float2*)(xtn + (size_t)idx.w * CIN) + lane);
                }
            }

            // -- consume k-slice ks of tap t --
            {
                const uint32_t aswz = ((uint32_t)(ks * 2) + khalf) ^ (uint32_t)g8;
                const uint32_t aoff = ca_row * 128 + (aswz << 4);
                uint32_t ah0, ah1, ah2, ah3, al0, al1, al2, al3;
                LDSM4(ah0, ah1, ah2, ah3, aH + aoff);
                LDSM4(al0, al1, al2, al3, aL + aoff);
                const uint32_t brow = (uint32_t)(ks * 16 + ((sel & 1) ? 8 : 0) + g8);
                #pragma unroll
                for (int ntp = 0; ntp < 4; ntp++) {
                    const uint32_t bswz = ((uint32_t)(ntp * 2) + khalf) ^ (uint32_t)g8;
                    uint32_t b0, b1, b2, b3;
                    LDSM4T(b0, b1, b2, b3, bH + brow * 128 + (bswz << 4));
                    MMA16816(d + (2 * ntp) * 4,     ah0, ah1, ah2, ah3, b0, b1);
                    MMA16816(d + (2 * ntp + 1) * 4, ah0, ah1, ah2, ah3, b2, b3);
                    MMA16816(d + (2 * ntp) * 4,     al0, al1, al2, al3, b0, b1);
                    MMA16816(d + (2 * ntp + 1) * 4, al0, al1, al2, al3, b2, b3);
                    uint32_t c0, c1, c2, c3;
                    LDSM4T(c0, c1, c2, c3, bL + brow * 128 + (bswz << 4));
                    MMA16816(d + (2 * ntp) * 4,     ah0, ah1, ah2, ah3, c0, c1);
                    MMA16816(d + (2 * ntp + 1) * 4, ah0, ah1, ah2, ah3, c2, c3);
                }
            }

            // -- combine + STS chunk into stage s1 --
            if (hasNext) {
                #pragma unroll
                for (int j = 0; j < 4; j++) {
                    const int px = wp0 + ks * 4 + j;
                    const float4 w = *(const float4*)(smem + CBUF + px * 32 + 16);
                    float vx = w.x * v[4 * j].x;
                    vx = fmaf(w.y, v[4 * j + 1].x, vx);
                    vx = fmaf(w.z, v[4 * j + 2].x, vx);
                    vx = fmaf(w.w, v[4 * j + 3].x, vx);
                    float vy = w.x * v[4 * j].y;
                    vy = fmaf(w.y, v[4 * j + 1].y, vy);
                    vy = fmaf(w.z, v[4 * j + 2].y, vy);
                    vy = fmaf(w.w, v[4 * j + 3].y, vy);
                    uint32_t hi2, lo2;
                    split_pair(vx, vy, hi2, lo2);
                    const uint32_t byte = (uint32_t)(px * 128 + ((((lane >> 2) ^ (px & 7))) << 4) + (lane & 3) * 4);
                    *(uint32_t*)(smem + A_ST(s1) + byte)            = hi2;
                    *(uint32_t*)(smem + A_ST(s1) + A_LO_OFF + byte) = lo2;
                }
            }
        }

        if (hasNext) CPWAIT0();
        __syncthreads();
    }

    // ---- epilogue ----
    const int r0 = wp0 + (lane >> 2);
    const float* bs = (const float*)(smem + BIAS_OFF);
    float* op = out + (size_t)n * COUT * HW + ho * WW;
    #pragma unroll
    for (int nt = 0; nt < 8; nt++) {
        const int c0 = nt * 8 + (lane & 3) * 2;
        const float2 bb = *(const float2*)(bs + c0);
        op[c0 * HW + r0]           = d[nt * 4 + 0] + bb.x;
        op[(c0 + 1) * HW + r0]     = d[nt * 4 + 1] + bb.y;
        op[c0 * HW + r0 + 8]       = d[nt * 4 + 2] + bb.x;
        op[(c0 + 1) * HW + r0 + 8] = d[nt * 4 + 3] + bb.y;
    }
}

extern "C" void kernel_launch(void* const* d_in, const int* in_sizes, int n_in,
                              void* d_out, int out_size) {
    const float* x      = (const float*)d_in[0];
    const float* offset = (const float*)d_in[1];
    const float* mask   = (const float*)d_in[2];
    const float* weight = (const float*)d_in[3];
    const float* bias   = (const float*)d_in[4];
    float* out = (float*)d_out;

    prep_kernel<<<TBLOCKS + NTAP, 256>>>(x, weight);

    cudaFuncSetAttribute(dcn_mma_kernel,
                         cudaFuncAttributeMaxDynamicSharedMemorySize, SMEM_BYTES);
    dcn_mma_kernel<<<NB * HH, THREADS, SMEM_BYTES>>>(offset, mask, bias, out);
}